// round 3
// baseline (speedup 1.0000x reference)
#include <cuda_runtime.h>
#include <cstdint>

#define DIM 64
#define CHUNKS 16   // float4 chunks per row (64 floats / 4)

// 0 = indices are int32, 1 = indices are int64
__device__ int g_idx64;

// ---------------------------------------------------------------------------
// init: out[i] = bias (so epilogue is a pure relu) + index-width probe.
// int64 values in [0,1e5): odd 32-bit words are always 0 (high halves).
// int32 random values: P(4 specific words == 0) ~ 1e-20.
// ---------------------------------------------------------------------------
__global__ void init_kernel(float4* __restrict__ out,
                            const float4* __restrict__ bias4, int n4,
                            const unsigned int* __restrict__ s0_words) {
    int i = blockIdx.x * blockDim.x + threadIdx.x;
    if (i == 0) {
        bool i64 = (s0_words[1] == 0u) && (s0_words[3] == 0u) &&
                   (s0_words[5] == 0u) && (s0_words[7] == 0u);
        g_idx64 = i64 ? 1 : 0;
    }
    if (i < n4) out[i] = __ldg(&bias4[i & 15]);
}

__device__ __forceinline__ int load_idx32(const void* p, int i, int idx64) {
    // values are < 2^31, so the low 32-bit word suffices in both layouts
    if (idx64)
        return ((const int*)p)[2 * i];
    else
        return ((const int*)p)[i];
}

// ---------------------------------------------------------------------------
// gather + scatter-add for ONE relation.
// One thread = one (edge, float4-chunk).
// ---------------------------------------------------------------------------
__global__ void __launch_bounds__(256)
scatter_rel_kernel(const float* __restrict__ emb,
                   const void* __restrict__ sp,
                   const void* __restrict__ dp,
                   float* __restrict__ outBase,   // already offset per ntype
                   int nE)
{
    int g = blockIdx.x * blockDim.x + threadIdx.x;
    int edge = g >> 4;
    int c    = g & 15;
    if (edge >= nE) return;

    const int idx64 = g_idx64;
    long long src = load_idx32(sp, edge, idx64);
    long long dst = load_idx32(dp, edge, idx64);

    const float4 v =
        *reinterpret_cast<const float4*>(emb + src * DIM + (long long)c * 4);
    float* p = outBase + dst * DIM + (long long)c * 4;

    // vector f32 reduction (no return) — sm_90+ red.global.add.v4.f32
    asm volatile("red.global.add.v4.f32 [%0], {%1,%2,%3,%4};"
                 :: "l"(p), "f"(v.x), "f"(v.y), "f"(v.z), "f"(v.w)
                 : "memory");
}

// ---------------------------------------------------------------------------
// epilogue: out = relu(out), float4-vectorized (bias already folded in init).
// ---------------------------------------------------------------------------
__global__ void relu_kernel(float4* __restrict__ out, int n4) {
    int i = blockIdx.x * blockDim.x + threadIdx.x;
    if (i >= n4) return;
    float4 v = out[i];
    v.x = fmaxf(v.x, 0.f);
    v.y = fmaxf(v.y, 0.f);
    v.z = fmaxf(v.z, 0.f);
    v.w = fmaxf(v.w, 0.f);
    out[i] = v;
}

// ---------------------------------------------------------------------------
// kernel_launch
// input order (metadata): embed0..embed3, h_bias, src0,dst0, src1,dst1,
//                         src2,dst2, src3,dst3
// relations: r0: embed0[src0] -> h_B ; r1: embed1[src1] -> h_A ;
//            r2: embed2[src2] -> h_A ; r3: embed3[src3] -> h_B
// ---------------------------------------------------------------------------
extern "C" void kernel_launch(void* const* d_in, const int* in_sizes, int n_in,
                              void* d_out, int out_size) {
    const float* e0 = (const float*)d_in[0];
    const float* e1 = (const float*)d_in[1];
    const float* e2 = (const float*)d_in[2];
    const float* e3 = (const float*)d_in[3];
    const float* bias = (const float*)d_in[4];

    const long long nN = in_sizes[0] / DIM;   // 100000
    const int       nE = in_sizes[5];         // 500000
    const int       n4 = out_size / 4;        // 2*N*16 float4

    float* out  = (float*)d_out;
    float* outA = out;                 // h_A at ntype index 0
    float* outB = out + nN * DIM;      // h_B at ntype index 1

    const int T = 256;
    const int scatterBlocks = (nE * CHUNKS + T - 1) / T;

    // 1) init out with bias + probe index width
    init_kernel<<<(n4 + T - 1) / T, T>>>((float4*)out, (const float4*)bias,
                                         n4, (const unsigned int*)d_in[5]);

    // 2) scatter-add, one launch per relation
    scatter_rel_kernel<<<scatterBlocks, T>>>(e0, d_in[5], d_in[6], outB, nE);
    scatter_rel_kernel<<<scatterBlocks, T>>>(e1, d_in[7], d_in[8], outA, nE);
    scatter_rel_kernel<<<scatterBlocks, T>>>(e2, d_in[9], d_in[10], outA, nE);
    scatter_rel_kernel<<<scatterBlocks, T>>>(e3, d_in[11], d_in[12], outB, nE);

    // 3) relu
    relu_kernel<<<(n4 + T - 1) / T, T>>>((float4*)out, n4);
}

// round 4
// speedup vs baseline: 1.5525x; 1.5525x over previous
#include <cuda_runtime.h>
#include <cstdint>

#define DIM    64
#define CHUNKS 16            // float4 chunks per row
#define NMAX   100000        // nodes per ntype (static scratch sizing)
#define EMAX   500000        // edges per relation
#define SCAN_B 1024

// ---------------------------------------------------------------------------
// scratch (device globals — no allocation)
// ---------------------------------------------------------------------------
__device__ int g_idx64;                    // 0 = int32 indices, 1 = int64
__device__ int g_cnt[2 * NMAX];            // per-bucket counts
__device__ int g_off[2 * NMAX + 1];        // exclusive offsets
__device__ int g_cur[2 * NMAX];            // write cursors for permute
__device__ int g_entries[4 * EMAX];        // src | (tableFlag<<30), bucket-sorted
__device__ int g_bsum[256];                // scan block sums

// ---------------------------------------------------------------------------
__device__ __forceinline__ int load_idx32(const void* p, int i, int idx64) {
    // values < 2^31: low word suffices in both layouts
    return idx64 ? ((const int*)p)[2 * i] : ((const int*)p)[i];
}

// relation -> (ntype, tableFlag):  r0:(B,0) r1:(A,0) r2:(A,1) r3:(B,1)
__device__ __forceinline__ int rel_ntype(int r) { return (r == 1 || r == 2) ? 0 : 1; }
__device__ __forceinline__ int rel_flag(int r)  { return (r >= 2) ? 1 : 0; }

// ---------------------------------------------------------------------------
// 0) zero counters + probe index width (odd 32-bit words of int64 idx are 0)
// ---------------------------------------------------------------------------
__global__ void zero_probe_kernel(int nb, const unsigned int* __restrict__ s0w) {
    int i = blockIdx.x * blockDim.x + threadIdx.x;
    if (i == 0) {
        bool i64 = (s0w[1] == 0u) && (s0w[3] == 0u) &&
                   (s0w[5] == 0u) && (s0w[7] == 0u);
        g_idx64 = i64 ? 1 : 0;
    }
    if (i < nb) g_cnt[i] = 0;
}

// ---------------------------------------------------------------------------
// 1) histogram over dst (gridDim.y = relation). atomicAdd w/o return -> RED
// ---------------------------------------------------------------------------
__global__ void hist_kernel(const void* __restrict__ d0, const void* __restrict__ d1,
                            const void* __restrict__ d2, const void* __restrict__ d3,
                            int nE, int nN) {
    int e = blockIdx.x * blockDim.x + threadIdx.x;
    if (e >= nE) return;
    int r = blockIdx.y;
    const void* dp = (r == 0) ? d0 : (r == 1) ? d1 : (r == 2) ? d2 : d3;
    int dst = load_idx32(dp, e, g_idx64);
    atomicAdd(&g_cnt[rel_ntype(r) * nN + dst], 1);
}

// ---------------------------------------------------------------------------
// 2) exclusive scan of g_cnt[0..n) into g_off (3 kernels)
// ---------------------------------------------------------------------------
__global__ void scan1_kernel(int n) {
    __shared__ int sa[SCAN_B], sb[SCAN_B];
    int t = threadIdx.x;
    int i = blockIdx.x * SCAN_B + t;
    int v = (i < n) ? g_cnt[i] : 0;
    sa[t] = v;
    __syncthreads();
    int* in = sa; int* out = sb;
    for (int off = 1; off < SCAN_B; off <<= 1) {
        out[t] = in[t] + (t >= off ? in[t - off] : 0);
        __syncthreads();
        int* tmp = in; in = out; out = tmp;
    }
    int incl = in[t];
    if (i < n) g_off[i] = incl - v;       // exclusive (block-local)
    if (t == SCAN_B - 1) g_bsum[blockIdx.x] = incl;
}

__global__ void scan2_kernel(int nb) {   // nb <= 256
    __shared__ int sa[256], sb[256];
    int t = threadIdx.x;
    int v = (t < nb) ? g_bsum[t] : 0;
    sa[t] = v;
    __syncthreads();
    int* in = sa; int* out = sb;
    for (int off = 1; off < 256; off <<= 1) {
        out[t] = in[t] + (t >= off ? in[t - off] : 0);
        __syncthreads();
        int* tmp = in; in = out; out = tmp;
    }
    if (t < nb) g_bsum[t] = in[t] - v;   // exclusive block bases
}

__global__ void scan3_kernel(int n) {
    int i = blockIdx.x * SCAN_B + threadIdx.x;
    if (i >= n) return;
    int o = g_off[i] + g_bsum[blockIdx.x];
    g_off[i] = o;
    g_cur[i] = o;
    if (i == n - 1) g_off[n] = o + g_cnt[i];
}

// ---------------------------------------------------------------------------
// 3) permute: bucket-sort edges; entry = src | (tableFlag << 30)
// ---------------------------------------------------------------------------
__global__ void permute_kernel(const void* __restrict__ s0, const void* __restrict__ d0,
                               const void* __restrict__ s1, const void* __restrict__ d1,
                               const void* __restrict__ s2, const void* __restrict__ d2,
                               const void* __restrict__ s3, const void* __restrict__ d3,
                               int nE, int nN) {
    int e = blockIdx.x * blockDim.x + threadIdx.x;
    if (e >= nE) return;
    int r = blockIdx.y;
    const void* sp; const void* dp;
    switch (r) {
        case 0:  sp = s0; dp = d0; break;
        case 1:  sp = s1; dp = d1; break;
        case 2:  sp = s2; dp = d2; break;
        default: sp = s3; dp = d3; break;
    }
    const int idx64 = g_idx64;
    int src = load_idx32(sp, e, idx64);
    int dst = load_idx32(dp, e, idx64);
    int b = rel_ntype(r) * nN + dst;
    int pos = atomicAdd(&g_cur[b], 1);
    g_entries[pos] = src | (rel_flag(r) << 30);
}

// ---------------------------------------------------------------------------
// 4) accumulate in registers + bias + relu + single store.
//    thread = (bucket, float4-chunk). bucket < nN -> ntype A (tables e1/e2),
//    else ntype B (tables e0/e3). out layout [2, N, D] == bucket * 64.
// ---------------------------------------------------------------------------
__global__ void __launch_bounds__(256)
accum_kernel(const float* __restrict__ e0, const float* __restrict__ e1,
             const float* __restrict__ e2, const float* __restrict__ e3,
             const float4* __restrict__ bias4, float4* __restrict__ out4,
             int nN) {
    int g = blockIdx.x * blockDim.x + threadIdx.x;
    int b = g >> 4;
    int c = g & 15;
    if (b >= 2 * nN) return;

    const float* t0;
    const float* t1;
    if (b < nN) { t0 = e1; t1 = e2; }      // h_A
    else        { t0 = e0; t1 = e3; }      // h_B

    int jb = g_off[b];
    int je = g_off[b + 1];

    float4 acc = __ldg(&bias4[c]);
    int coff = c * 4;

    #pragma unroll 4
    for (int j = jb; j < je; j++) {
        int ent = g_entries[j];
        const float* tb = (ent & (1 << 30)) ? t1 : t0;
        int src = ent & 0x0FFFFFFF;
        const float4 v = *reinterpret_cast<const float4*>(tb + src * DIM + coff);
        acc.x += v.x; acc.y += v.y; acc.z += v.z; acc.w += v.w;
    }

    acc.x = fmaxf(acc.x, 0.f);
    acc.y = fmaxf(acc.y, 0.f);
    acc.z = fmaxf(acc.z, 0.f);
    acc.w = fmaxf(acc.w, 0.f);
    out4[(long long)b * CHUNKS + c] = acc;
}

// ---------------------------------------------------------------------------
// fallback path (atomic scatter, proven @157us) if shapes exceed scratch
// ---------------------------------------------------------------------------
__global__ void fb_init_kernel(float4* __restrict__ out,
                               const float4* __restrict__ bias4, int n4) {
    int i = blockIdx.x * blockDim.x + threadIdx.x;
    if (i < n4) out[i] = __ldg(&bias4[i & 15]);
}

__global__ void __launch_bounds__(256)
fb_scatter_kernel(const float* __restrict__ e0, const float* __restrict__ e1,
                  const float* __restrict__ e2, const float* __restrict__ e3,
                  const void* __restrict__ s0, const void* __restrict__ d0,
                  const void* __restrict__ s1, const void* __restrict__ d1,
                  const void* __restrict__ s2, const void* __restrict__ d2,
                  const void* __restrict__ s3, const void* __restrict__ d3,
                  float* __restrict__ out, int nE, long long nN) {
    int g = blockIdx.x * blockDim.x + threadIdx.x;
    int edge = g >> 4;
    int c = g & 15;
    if (edge >= nE) return;
    const float* emb; const void* sp; const void* dp; long long off;
    switch (blockIdx.y) {
        case 0:  emb = e0; sp = s0; dp = d0; off = nN * DIM; break;
        case 1:  emb = e1; sp = s1; dp = d1; off = 0;        break;
        case 2:  emb = e2; sp = s2; dp = d2; off = 0;        break;
        default: emb = e3; sp = s3; dp = d3; off = nN * DIM; break;
    }
    const int idx64 = g_idx64;
    long long src = load_idx32(sp, edge, idx64);
    long long dst = load_idx32(dp, edge, idx64);
    const float4 v = *reinterpret_cast<const float4*>(emb + src * DIM + (long long)c * 4);
    float* p = out + off + dst * DIM + (long long)c * 4;
    asm volatile("red.global.add.v4.f32 [%0], {%1,%2,%3,%4};"
                 :: "l"(p), "f"(v.x), "f"(v.y), "f"(v.z), "f"(v.w) : "memory");
}

__global__ void fb_relu_kernel(float4* __restrict__ out, int n4) {
    int i = blockIdx.x * blockDim.x + threadIdx.x;
    if (i >= n4) return;
    float4 v = out[i];
    v.x = fmaxf(v.x, 0.f); v.y = fmaxf(v.y, 0.f);
    v.z = fmaxf(v.z, 0.f); v.w = fmaxf(v.w, 0.f);
    out[i] = v;
}

// ---------------------------------------------------------------------------
// kernel_launch — inputs: embed0..3, h_bias, src0,dst0,...,src3,dst3
// ---------------------------------------------------------------------------
extern "C" void kernel_launch(void* const* d_in, const int* in_sizes, int n_in,
                              void* d_out, int out_size) {
    const float* e0 = (const float*)d_in[0];
    const float* e1 = (const float*)d_in[1];
    const float* e2 = (const float*)d_in[2];
    const float* e3 = (const float*)d_in[3];
    const float4* bias4 = (const float4*)d_in[4];

    const int nN = in_sizes[0] / DIM;      // 100000
    const int nE = in_sizes[5];            // 500000
    const int n4 = out_size / 4;

    float* out = (float*)d_out;
    const int T = 256;
    const int nb = 2 * nN;                               // buckets
    const int scanBlocks = (nb + SCAN_B - 1) / SCAN_B;   // 196

    // probe always needed
    zero_probe_kernel<<<(nb + T - 1) / T, T>>>(nb, (const unsigned int*)d_in[5]);

    if (nN <= NMAX && nE <= EMAX && scanBlocks <= 256) {
        // --- CSR gather path ---
        dim3 ghist((nE + T - 1) / T, 4);
        hist_kernel<<<ghist, T>>>(d_in[6], d_in[8], d_in[10], d_in[12], nE, nN);

        scan1_kernel<<<scanBlocks, SCAN_B>>>(nb);
        scan2_kernel<<<1, 256>>>(scanBlocks);
        scan3_kernel<<<scanBlocks, SCAN_B>>>(nb);

        permute_kernel<<<ghist, T>>>(d_in[5], d_in[6], d_in[7], d_in[8],
                                     d_in[9], d_in[10], d_in[11], d_in[12],
                                     nE, nN);

        int work = nb * CHUNKS;
        accum_kernel<<<(work + T - 1) / T, T>>>(e0, e1, e2, e3, bias4,
                                                (float4*)out, nN);
    } else {
        // --- fallback: atomic scatter ---
        fb_init_kernel<<<(n4 + T - 1) / T, T>>>((float4*)out, bias4, n4);
        int work = nE * CHUNKS;
        dim3 grid((work + T - 1) / T, 4);
        fb_scatter_kernel<<<grid, T>>>(e0, e1, e2, e3,
                                       d_in[5], d_in[6], d_in[7], d_in[8],
                                       d_in[9], d_in[10], d_in[11], d_in[12],
                                       out, nE, nN);
        fb_relu_kernel<<<(n4 + T - 1) / T, T>>>((float4*)out, n4);
    }
}

// round 5
// speedup vs baseline: 1.5549x; 1.0016x over previous
#include <cuda_runtime.h>
#include <cstdint>

#define DIM    64
#define CHUNKS 16            // float4 chunks per row
#define NMAX   100000        // nodes per ntype (static scratch sizing)
#define EMAX   500000        // edges per relation
#define KSLOT  64            // slots per bucket (deg ~Poisson(10); overflow handled)

// ---------------------------------------------------------------------------
// scratch (device globals — no runtime allocation)
// ---------------------------------------------------------------------------
__device__ int g_idx64;                       // 0 = int32 indices, 1 = int64
__device__ int g_cur[2 * NMAX];               // per-bucket write cursors
__device__ int g_entries[2 * NMAX * KSLOT];   // src | (tableFlag<<30), slotted

// ---------------------------------------------------------------------------
__device__ __forceinline__ int load_idx32(const void* p, int i, int idx64) {
    // index values < 2^31: low word suffices for both int32 and int64 layouts
    return idx64 ? ((const int*)p)[2 * i] : ((const int*)p)[i];
}

// ---------------------------------------------------------------------------
// 1) init: out = bias, zero cursors, probe index width.
//    int64 values in [0,1e5): odd 32-bit words are 0; int32 random: ~never.
// ---------------------------------------------------------------------------
__global__ void init_kernel(float4* __restrict__ out4,
                            const float4* __restrict__ bias4,
                            int n4, int nb,
                            const unsigned int* __restrict__ s0w) {
    int i = blockIdx.x * blockDim.x + threadIdx.x;
    if (i == 0) {
        bool i64 = (s0w[1] == 0u) && (s0w[3] == 0u) &&
                   (s0w[5] == 0u) && (s0w[7] == 0u);
        g_idx64 = i64 ? 1 : 0;
    }
    if (i < nb) g_cur[i] = 0;
    if (i < n4) out4[i] = __ldg(&bias4[i & 15]);
}

// ---------------------------------------------------------------------------
// 2) permute: slot edges into per-bucket regions. gridDim.y = relation.
//    relation -> (dst ntype, src table): r0:(B,e0) r1:(A,e1) r2:(A,e2) r3:(B,e3)
//    bucket b = ntype*nN + dst; table flag bit30 selects e2/e3 vs e0/e1.
//    Overflow (pos >= KSLOT, ~P=1e-30): red-add the row straight into out.
// ---------------------------------------------------------------------------
__global__ void __launch_bounds__(256)
permute_kernel(const float* __restrict__ e0, const float* __restrict__ e1,
               const float* __restrict__ e2, const float* __restrict__ e3,
               const void* __restrict__ s0, const void* __restrict__ d0,
               const void* __restrict__ s1, const void* __restrict__ d1,
               const void* __restrict__ s2, const void* __restrict__ d2,
               const void* __restrict__ s3, const void* __restrict__ d3,
               float* __restrict__ out, int nE, int nN) {
    int e = blockIdx.x * blockDim.x + threadIdx.x;
    if (e >= nE) return;
    int r = blockIdx.y;

    const void* sp; const void* dp; int ntype; int flag; const float* emb;
    switch (r) {
        case 0:  sp = s0; dp = d0; ntype = 1; flag = 0; emb = e0; break;
        case 1:  sp = s1; dp = d1; ntype = 0; flag = 0; emb = e1; break;
        case 2:  sp = s2; dp = d2; ntype = 0; flag = 1; emb = e2; break;
        default: sp = s3; dp = d3; ntype = 1; flag = 1; emb = e3; break;
    }

    const int idx64 = g_idx64;
    int src = load_idx32(sp, e, idx64);
    int dst = load_idx32(dp, e, idx64);
    int b = ntype * nN + dst;

    int pos = atomicAdd(&g_cur[b], 1);
    if (pos < KSLOT) {
        g_entries[b * KSLOT + pos] = src | (flag << 30);
    } else {
        // overflow: apply directly to out (extremely rare; keeps correctness)
        const float* row = emb + (long long)src * DIM;
        float* o = out + (long long)b * DIM;
        #pragma unroll
        for (int c = 0; c < CHUNKS; c++) {
            const float4 v = *reinterpret_cast<const float4*>(row + c * 4);
            asm volatile("red.global.add.v4.f32 [%0], {%1,%2,%3,%4};"
                         :: "l"(o + c * 4), "f"(v.x), "f"(v.y), "f"(v.z), "f"(v.w)
                         : "memory");
        }
    }
}

// ---------------------------------------------------------------------------
// 3) accumulate: thread = (bucket, float4-chunk). Seed from out (bias + any
//    overflow), register-accumulate gathered rows, relu, single store.
//    bucket < nN -> h_A (tables e1/e2), else h_B (tables e0/e3).
// ---------------------------------------------------------------------------
__global__ void __launch_bounds__(256)
accum_kernel(const float* __restrict__ e0, const float* __restrict__ e1,
             const float* __restrict__ e2, const float* __restrict__ e3,
             float4* __restrict__ out4, int nN) {
    int g = blockIdx.x * blockDim.x + threadIdx.x;
    int b = g >> 4;
    int c = g & 15;
    if (b >= 2 * nN) return;

    const float* t0;
    const float* t1;
    if (b < nN) { t0 = e1; t1 = e2; }      // h_A
    else        { t0 = e0; t1 = e3; }      // h_B

    int n = g_cur[b];
    if (n > KSLOT) n = KSLOT;

    long long oi = (long long)b * CHUNKS + c;
    float4 acc = out4[oi];
    const int* ep = g_entries + b * KSLOT;
    int coff = c * 4;

    #pragma unroll 4
    for (int j = 0; j < n; j++) {
        int ent = ep[j];
        const float* tb = (ent & (1 << 30)) ? t1 : t0;
        int src = ent & 0x0FFFFFFF;
        const float4 v = *reinterpret_cast<const float4*>(tb + (long long)src * DIM + coff);
        acc.x += v.x; acc.y += v.y; acc.z += v.z; acc.w += v.w;
    }

    acc.x = fmaxf(acc.x, 0.f);
    acc.y = fmaxf(acc.y, 0.f);
    acc.z = fmaxf(acc.z, 0.f);
    acc.w = fmaxf(acc.w, 0.f);
    out4[oi] = acc;
}

// ---------------------------------------------------------------------------
// fallback path (atomic scatter, proven) if shapes exceed static scratch
// ---------------------------------------------------------------------------
__global__ void __launch_bounds__(256)
fb_scatter_kernel(const float* __restrict__ e0, const float* __restrict__ e1,
                  const float* __restrict__ e2, const float* __restrict__ e3,
                  const void* __restrict__ s0, const void* __restrict__ d0,
                  const void* __restrict__ s1, const void* __restrict__ d1,
                  const void* __restrict__ s2, const void* __restrict__ d2,
                  const void* __restrict__ s3, const void* __restrict__ d3,
                  float* __restrict__ out, int nE, long long nN) {
    int g = blockIdx.x * blockDim.x + threadIdx.x;
    int edge = g >> 4;
    int c = g & 15;
    if (edge >= nE) return;
    const float* emb; const void* sp; const void* dp; long long off;
    switch (blockIdx.y) {
        case 0:  emb = e0; sp = s0; dp = d0; off = nN * DIM; break;
        case 1:  emb = e1; sp = s1; dp = d1; off = 0;        break;
        case 2:  emb = e2; sp = s2; dp = d2; off = 0;        break;
        default: emb = e3; sp = s3; dp = d3; off = nN * DIM; break;
    }
    const int idx64 = g_idx64;
    long long src = load_idx32(sp, edge, idx64);
    long long dst = load_idx32(dp, edge, idx64);
    const float4 v = *reinterpret_cast<const float4*>(emb + src * DIM + (long long)c * 4);
    float* p = out + off + dst * DIM + (long long)c * 4;
    asm volatile("red.global.add.v4.f32 [%0], {%1,%2,%3,%4};"
                 :: "l"(p), "f"(v.x), "f"(v.y), "f"(v.z), "f"(v.w) : "memory");
}

__global__ void fb_relu_kernel(float4* __restrict__ out, int n4) {
    int i = blockIdx.x * blockDim.x + threadIdx.x;
    if (i >= n4) return;
    float4 v = out[i];
    v.x = fmaxf(v.x, 0.f); v.y = fmaxf(v.y, 0.f);
    v.z = fmaxf(v.z, 0.f); v.w = fmaxf(v.w, 0.f);
    out[i] = v;
}

// ---------------------------------------------------------------------------
// kernel_launch — inputs: embed0..3, h_bias, src0,dst0,...,src3,dst3
// ---------------------------------------------------------------------------
extern "C" void kernel_launch(void* const* d_in, const int* in_sizes, int n_in,
                              void* d_out, int out_size) {
    const float* e0 = (const float*)d_in[0];
    const float* e1 = (const float*)d_in[1];
    const float* e2 = (const float*)d_in[2];
    const float* e3 = (const float*)d_in[3];
    const float4* bias4 = (const float4*)d_in[4];

    const int nN = in_sizes[0] / DIM;      // 100000
    const int nE = in_sizes[5];            // 500000
    const int n4 = out_size / 4;           // 2*N*16

    float* out = (float*)d_out;
    const int T = 256;
    const int nb = 2 * nN;

    if (nN <= NMAX && nE <= EMAX) {
        // 1) init out with bias + zero cursors + probe
        init_kernel<<<(n4 + T - 1) / T, T>>>((float4*)out, bias4, n4, nb,
                                             (const unsigned int*)d_in[5]);
        // 2) slot edges into buckets
        dim3 gperm((nE + T - 1) / T, 4);
        permute_kernel<<<gperm, T>>>(e0, e1, e2, e3,
                                     d_in[5], d_in[6], d_in[7], d_in[8],
                                     d_in[9], d_in[10], d_in[11], d_in[12],
                                     out, nE, nN);
        // 3) gather-accumulate + relu + store
        int work = nb * CHUNKS;
        accum_kernel<<<(work + T - 1) / T, T>>>(e0, e1, e2, e3,
                                                (float4*)out, nN);
    } else {
        // fallback: atomic scatter
        init_kernel<<<(n4 + T - 1) / T, T>>>((float4*)out, bias4, n4, 0,
                                             (const unsigned int*)d_in[5]);
        int work = nE * CHUNKS;
        dim3 grid((work + T - 1) / T, 4);
        fb_scatter_kernel<<<grid, T>>>(e0, e1, e2, e3,
                                       d_in[5], d_in[6], d_in[7], d_in[8],
                                       d_in[9], d_in[10], d_in[11], d_in[12],
                                       out, nE, nN);
        fb_relu_kernel<<<(n4 + T - 1) / T, T>>>((float4*)out, n4);
    }
}

// round 6
// speedup vs baseline: 1.7220x; 1.1075x over previous
#include <cuda_runtime.h>
#include <cstdint>

#define DIM     64
#define CHUNKS  16            // float4 chunks per row
#define NMAX    100000        // nodes per ntype (static scratch sizing)
#define EMAX    500000        // edges per relation
#define KSLOT   40            // slots per bucket (deg ~Poisson(10))
#define SPILLC  (4 * EMAX)    // spill capacity = all edges (unconditional)

// ---------------------------------------------------------------------------
// scratch (device globals — no runtime allocation)
// ---------------------------------------------------------------------------
__device__ int  g_idx64;                      // 0 = int32 indices, 1 = int64
__device__ int  g_nover;                      // overflow edge count
__device__ int  g_cur[2 * NMAX];              // per-bucket write cursors
__device__ int  g_entries[2 * NMAX * KSLOT];  // src | (tableFlag<<30), slotted
__device__ int2 g_spill[SPILLC];              // (bucket, src|flag<<30)

// ---------------------------------------------------------------------------
__device__ __forceinline__ int load_idx32(const void* p, int i, int idx64) {
    // index values < 2^31: low word suffices for both int32 and int64 layouts
    return idx64 ? ((const int*)p)[2 * i] : ((const int*)p)[i];
}

// ---------------------------------------------------------------------------
// 1) init: zero cursors + overflow count, probe index width.
//    int64 values in [0,1e5): odd 32-bit words are 0; int32 random: ~never.
// ---------------------------------------------------------------------------
__global__ void init_kernel(int nb, const unsigned int* __restrict__ s0w) {
    int i = blockIdx.x * blockDim.x + threadIdx.x;
    if (i == 0) {
        bool i64 = (s0w[1] == 0u) && (s0w[3] == 0u) &&
                   (s0w[5] == 0u) && (s0w[7] == 0u);
        g_idx64 = i64 ? 1 : 0;
        g_nover = 0;
    }
    if (i < nb) g_cur[i] = 0;
}

// ---------------------------------------------------------------------------
// 2) permute: slot edges into per-bucket regions. gridDim.y = relation.
//    relation -> (dst ntype, src table): r0:(B,e0) r1:(A,e1) r2:(A,e2) r3:(B,e3)
//    bucket b = ntype*nN + dst; table flag bit30 selects e2/e3 vs e0/e1.
//    Overflow (pos >= KSLOT, P~1e-14/bucket) goes to the spill list, which is
//    sized to hold every edge -> unconditionally correct.
// ---------------------------------------------------------------------------
__global__ void __launch_bounds__(256)
permute_kernel(const void* __restrict__ s0, const void* __restrict__ d0,
               const void* __restrict__ s1, const void* __restrict__ d1,
               const void* __restrict__ s2, const void* __restrict__ d2,
               const void* __restrict__ s3, const void* __restrict__ d3,
               int nE, int nN) {
    int e = blockIdx.x * blockDim.x + threadIdx.x;
    if (e >= nE) return;
    int r = blockIdx.y;

    const void* sp; const void* dp; int ntype; int flag;
    switch (r) {
        case 0:  sp = s0; dp = d0; ntype = 1; flag = 0; break;
        case 1:  sp = s1; dp = d1; ntype = 0; flag = 0; break;
        case 2:  sp = s2; dp = d2; ntype = 0; flag = 1; break;
        default: sp = s3; dp = d3; ntype = 1; flag = 1; break;
    }

    const int idx64 = g_idx64;
    int src = load_idx32(sp, e, idx64);
    int dst = load_idx32(dp, e, idx64);
    int b = ntype * nN + dst;
    int ent = src | (flag << 30);

    int pos = atomicAdd(&g_cur[b], 1);
    if (pos < KSLOT) {
        g_entries[b * KSLOT + pos] = ent;
    } else {
        int spos = atomicAdd(&g_nover, 1);   // spill holds ALL edges worst-case
        g_spill[spos] = make_int2(b, ent);
    }
}

// ---------------------------------------------------------------------------
// 3) accumulate: thread = (bucket, float4-chunk). Seed = bias (broadcast),
//    register-accumulate gathered rows, relu, single store.
//    bucket < nN -> h_A (tables e1/e2), else h_B (tables e0/e3).
// ---------------------------------------------------------------------------
__global__ void __launch_bounds__(256)
accum_kernel(const float* __restrict__ e0, const float* __restrict__ e1,
             const float* __restrict__ e2, const float* __restrict__ e3,
             const float4* __restrict__ bias4, float4* __restrict__ out4,
             int nN) {
    int g = blockIdx.x * blockDim.x + threadIdx.x;
    int b = g >> 4;
    int c = g & 15;
    if (b >= 2 * nN) return;

    const float* t0;
    const float* t1;
    if (b < nN) { t0 = e1; t1 = e2; }      // h_A
    else        { t0 = e0; t1 = e3; }      // h_B

    int n = g_cur[b];
    if (n > KSLOT) n = KSLOT;

    float4 acc = __ldg(&bias4[c]);
    const int* ep = g_entries + b * KSLOT;
    int coff = c * 4;

    #pragma unroll 4
    for (int j = 0; j < n; j++) {
        int ent = ep[j];
        const float* tb = (ent & (1 << 30)) ? t1 : t0;
        int src = ent & 0x0FFFFFFF;
        const float4 v =
            *reinterpret_cast<const float4*>(tb + (long long)src * DIM + coff);
        acc.x += v.x; acc.y += v.y; acc.z += v.z; acc.w += v.w;
    }

    // overflow path: never taken in practice (one broadcast-cached load)
    int nov = g_nover;
    if (nov > 0) {
        for (int j = 0; j < nov; j++) {
            int2 se = g_spill[j];
            if (se.x == b) {
                const float* tb = (se.y & (1 << 30)) ? t1 : t0;
                int src = se.y & 0x0FFFFFFF;
                const float4 v =
                    *reinterpret_cast<const float4*>(tb + (long long)src * DIM + coff);
                acc.x += v.x; acc.y += v.y; acc.z += v.z; acc.w += v.w;
            }
        }
    }

    acc.x = fmaxf(acc.x, 0.f);
    acc.y = fmaxf(acc.y, 0.f);
    acc.z = fmaxf(acc.z, 0.f);
    acc.w = fmaxf(acc.w, 0.f);
    out4[(long long)b * CHUNKS + c] = acc;
}

// ---------------------------------------------------------------------------
// fallback path (atomic scatter, proven) if shapes exceed static scratch
// ---------------------------------------------------------------------------
__global__ void fb_init_kernel(float4* __restrict__ out,
                               const float4* __restrict__ bias4, int n4) {
    int i = blockIdx.x * blockDim.x + threadIdx.x;
    if (i < n4) out[i] = __ldg(&bias4[i & 15]);
}

__global__ void __launch_bounds__(256)
fb_scatter_kernel(const float* __restrict__ e0, const float* __restrict__ e1,
                  const float* __restrict__ e2, const float* __restrict__ e3,
                  const void* __restrict__ s0, const void* __restrict__ d0,
                  const void* __restrict__ s1, const void* __restrict__ d1,
                  const void* __restrict__ s2, const void* __restrict__ d2,
                  const void* __restrict__ s3, const void* __restrict__ d3,
                  float* __restrict__ out, int nE, long long nN) {
    int g = blockIdx.x * blockDim.x + threadIdx.x;
    int edge = g >> 4;
    int c = g & 15;
    if (edge >= nE) return;
    const float* emb; const void* sp; const void* dp; long long off;
    switch (blockIdx.y) {
        case 0:  emb = e0; sp = s0; dp = d0; off = nN * DIM; break;
        case 1:  emb = e1; sp = s1; dp = d1; off = 0;        break;
        case 2:  emb = e2; sp = s2; dp = d2; off = 0;        break;
        default: emb = e3; sp = s3; dp = d3; off = nN * DIM; break;
    }
    const int idx64 = g_idx64;
    long long src = load_idx32(sp, edge, idx64);
    long long dst = load_idx32(dp, edge, idx64);
    const float4 v =
        *reinterpret_cast<const float4*>(emb + src * DIM + (long long)c * 4);
    float* p = out + off + dst * DIM + (long long)c * 4;
    asm volatile("red.global.add.v4.f32 [%0], {%1,%2,%3,%4};"
                 :: "l"(p), "f"(v.x), "f"(v.y), "f"(v.z), "f"(v.w) : "memory");
}

__global__ void fb_relu_kernel(float4* __restrict__ out, int n4) {
    int i = blockIdx.x * blockDim.x + threadIdx.x;
    if (i >= n4) return;
    float4 v = out[i];
    v.x = fmaxf(v.x, 0.f); v.y = fmaxf(v.y, 0.f);
    v.z = fmaxf(v.z, 0.f); v.w = fmaxf(v.w, 0.f);
    out[i] = v;
}

// ---------------------------------------------------------------------------
// kernel_launch — inputs: embed0..3, h_bias, src0,dst0,...,src3,dst3
// ---------------------------------------------------------------------------
extern "C" void kernel_launch(void* const* d_in, const int* in_sizes, int n_in,
                              void* d_out, int out_size) {
    const float* e0 = (const float*)d_in[0];
    const float* e1 = (const float*)d_in[1];
    const float* e2 = (const float*)d_in[2];
    const float* e3 = (const float*)d_in[3];
    const float4* bias4 = (const float4*)d_in[4];

    const int nN = in_sizes[0] / DIM;      // 100000
    const int nE = in_sizes[5];            // 500000
    const int n4 = out_size / 4;           // 2*N*16

    float* out = (float*)d_out;
    const int T = 256;
    const int nb = 2 * nN;

    if (nN <= NMAX && nE <= EMAX) {
        // 1) zero cursors + probe
        init_kernel<<<(nb + T - 1) / T, T>>>(nb, (const unsigned int*)d_in[5]);
        // 2) slot edges into buckets
        dim3 gperm((nE + T - 1) / T, 4);
        permute_kernel<<<gperm, T>>>(d_in[5], d_in[6], d_in[7], d_in[8],
                                     d_in[9], d_in[10], d_in[11], d_in[12],
                                     nE, nN);
        // 3) gather-accumulate + bias + relu + store
        int work = nb * CHUNKS;
        accum_kernel<<<(work + T - 1) / T, T>>>(e0, e1, e2, e3, bias4,
                                                (float4*)out, nN);
    } else {
        // fallback: atomic scatter (init_kernel still probes idx width)
        init_kernel<<<1, 32>>>(0, (const unsigned int*)d_in[5]);
        fb_init_kernel<<<(n4 + T - 1) / T, T>>>((float4*)out, bias4, n4);
        int work = nE * CHUNKS;
        dim3 grid((work + T - 1) / T, 4);
        fb_scatter_kernel<<<grid, T>>>(e0, e1, e2, e3,
                                       d_in[5], d_in[6], d_in[7], d_in[8],
                                       d_in[9], d_in[10], d_in[11], d_in[12],
                                       out, nE, nN);
        fb_relu_kernel<<<(n4 + T - 1) / T, T>>>((float4*)out, n4);
    }
}